// round 10
// baseline (speedup 1.0000x reference)
#include <cuda_runtime.h>
#include <math.h>

// ---------------------------------------------------------------------------
// NUFFT adjoint (Kaiser-Bessel gridding) for GB300 — round 10
// Hermitian packing moved INTO the scatter: grid stores C_p = He(G_2p) +
// i He(G_2p+1) directly (4 packed complex per cell, 32 MB). Each point
// scatters at k (pair-packed values) and at -k (conjugate-packed values);
// same atomic count as R9, but fft_x loses its mirror reads (128->32 MB),
// and zero/L2 footprint halves.
// ---------------------------------------------------------------------------

#define KGRID   1024
#define NIMG    512
#define MPTS    200000
#define JW      6
#define BETA_F  14.04f
#define PI_F    3.14159265358979f

#define NPACK   4                         // packed batch pairs per cell
#define GRID_F2 (KGRID * KGRID * NPACK)   // 4M float2 = 32 MB
#define PITCH   1026                      // smem row pitch (float2), even

#define TW_OFF1 0
#define TW_OFF2 12
#define TW_OFF3 60
#define TW_OFF4 252
#define TW_TOT  1020

__device__ float2 g_grid[GRID_F2];

// ---------------------------------------------------------------------------
__device__ __forceinline__ float bessel_i0(float x)
{
    if (x < 3.75f) {
        float t = x * (1.0f / 3.75f);
        t *= t;
        return 1.0f + t * (3.5156229f + t * (3.0899424f + t * (1.2067492f +
                     t * (0.2659732f + t * (0.0360768f + t * 0.0045813f)))));
    } else {
        float t = 3.75f / x;
        float p = 0.39894228f + t * (0.01328592f + t * (0.00225319f +
                  t * (-0.00157565f + t * (0.00916281f + t * (-0.02057706f +
                  t * (0.02635537f + t * (-0.01647633f + t * 0.00392377f)))))));
        return __expf(x) * rsqrtf(x) * p;
    }
}

// ---------------------------------------------------------------------------
// Zero the packed grid (32 MB). Also the L2 warm for the scatter's atomics.
// ---------------------------------------------------------------------------
__global__ void zero_kernel()
{
    float4* p = reinterpret_cast<float4*>(g_grid);
    const int n = GRID_F2 / 2;
    for (int i = blockIdx.x * blockDim.x + threadIdx.x; i < n;
         i += gridDim.x * blockDim.x)
        p[i] = make_float4(0.f, 0.f, 0.f, 0.f);
}

// ---------------------------------------------------------------------------
// Hermitian-packed gridding scatter: 8 threads per measurement.
//   s = cell sign (k vs -k), h = x-tap half, v = packed pair half (p=2v,2v+1)
//   18 red.v4.f32 per thread (same count as R9).
// Cell (kx,ky) stores C_p = He(G_2p)+i He(G_2p+1), p=0..3 (float2 each).
// Point contributes 0.5*w*(y_2p + i y_2p+1) at k and the conjugate-packed
// value 0.5*w*(conj(y_2p) + i conj(y_2p+1)) at -k.
// ---------------------------------------------------------------------------
__global__ __launch_bounds__(256)
void scatter_kernel(const float* __restrict__ yr, const float* __restrict__ yi,
                    const float* __restrict__ uv, const float* __restrict__ wts)
{
    const int gid = blockIdx.x * blockDim.x + threadIdx.x;
    const int m = gid >> 3;
    const int u = gid & 7;
    const int s = u & 1;                   // 0: +k, 1: -k (conjugate)
    const int h = (u >> 1) & 1;            // a in {3h, 3h+1, 3h+2}
    const int v = (u >> 2) & 1;            // packed p in {2v, 2v+1}
    if (m >= MPTS) return;

    const float2 c2 = reinterpret_cast<const float2*>(uv)[m];
    const float inv_i0b = 1.0f / bessel_i0(BETA_F);

    int ixv[3], iyv[JW];
    float wx[3], wy[JW];

    {   // axis 0: this thread's 3 taps (mirrored for s=1)
        float k  = c2.x / (2.0f * PI_F) * (float)KGRID;
        float km = floorf(k - 3.0f);
        #pragma unroll
        for (int j = 0; j < 3; j++) {
            int jj = 3 * h + j;
            float pt = km + (float)(jj + 1);
            float d  = k - pt;
            float arg = fmaxf(1.0f - d * d * (1.0f / 9.0f), 0.0f);
            wx[j] = bessel_i0(BETA_F * sqrtf(arg)) * inv_i0b;
            int idx = ((int)pt + KGRID) & (KGRID - 1);
            ixv[j] = s ? ((KGRID - idx) & (KGRID - 1)) : idx;
        }
    }
    {   // axis 1: all 6 taps (mirrored for s=1)
        float k  = c2.y / (2.0f * PI_F) * (float)KGRID;
        float km = floorf(k - 3.0f);
        #pragma unroll
        for (int j = 0; j < JW; j++) {
            float pt = km + (float)(j + 1);
            float d  = k - pt;
            float arg = fmaxf(1.0f - d * d * (1.0f / 9.0f), 0.0f);
            wy[j] = bessel_i0(BETA_F * sqrtf(arg)) * inv_i0b;
            int idx = ((int)pt + KGRID) & (KGRID - 1);
            iyv[j] = s ? ((KGRID - idx) & (KGRID - 1)) : idx;
        }
    }

    // batches 4v..4v+3 -> packed values p=2v (batches 4v,4v+1) and
    // p=2v+1 (batches 4v+2,4v+3); 0.5 of He folded into wt2.
    const int b0 = 4 * v;
    const float wt2 = 0.5f * wts[m];
    const float yr0 = yr[(b0 + 0) * MPTS + m], yi0 = yi[(b0 + 0) * MPTS + m];
    const float yr1 = yr[(b0 + 1) * MPTS + m], yi1 = yi[(b0 + 1) * MPTS + m];
    const float yr2 = yr[(b0 + 2) * MPTS + m], yi2 = yi[(b0 + 2) * MPTS + m];
    const float yr3 = yr[(b0 + 3) * MPTS + m], yi3 = yi[(b0 + 3) * MPTS + m];

    const float sgn = s ? -1.0f : 1.0f;
    const float cra = wt2 * (yr0 - sgn * yi1);
    const float cia = wt2 * (sgn * yi0 + yr1);
    const float crb = wt2 * (yr2 - sgn * yi3);
    const float cib = wt2 * (sgn * yi2 + yr3);

    #pragma unroll
    for (int a = 0; a < 3; a++) {
        const int rowbase = ixv[a] * KGRID;
        const float wxa = wx[a];
        #pragma unroll
        for (int c = 0; c < JW; c++) {
            const float w2 = wxa * wy[c];
            float* fp = reinterpret_cast<float*>(
                            &g_grid[(rowbase + iyv[c]) * NPACK]) + 4 * v;
            asm volatile(
                "red.global.add.v4.f32 [%0], {%1, %2, %3, %4};"
                :: "l"(fp),
                   "f"(w2 * cra), "f"(w2 * cia),
                   "f"(w2 * crb), "f"(w2 * cib)
                : "memory");
        }
    }
}

// ---------------------------------------------------------------------------
// Radix-4 FFT machinery (inverse, e^{+i})
// ---------------------------------------------------------------------------
__device__ __forceinline__ int digit_rev10(int i)
{
    int r = (int)(__brev((unsigned)i) >> 22);
    return ((r & 0x155) << 1) | ((r & 0x2AA) >> 1);
}

__device__ __forceinline__ float2 cmul(float2 a, float2 b)
{
    return make_float2(a.x * b.x - a.y * b.y, a.x * b.y + a.y * b.x);
}

__device__ __forceinline__ void init_tw(float2* tw, int tid, int nthr)
{
    for (int t = tid; t < 340; t += nthr) {
        int s, j, off;
        if      (t < 4)  { s = 1; j = t;      off = TW_OFF1; }
        else if (t < 20) { s = 2; j = t - 4;  off = TW_OFF2; }
        else if (t < 84) { s = 3; j = t - 20; off = TW_OFF3; }
        else             { s = 4; j = t - 84; off = TW_OFF4; }
        int em = j << (8 - 2 * s);
        float a = (float)em * (2.0f * PI_F / 1024.0f);
        float s1, c1, s2, c2, s3, c3;
        __sincosf(a, &s1, &c1);
        __sincosf(2.0f * a, &s2, &c2);
        __sincosf(3.0f * a, &s3, &c3);
        tw[off + 3 * j + 0] = make_float2(c1, s1);
        tw[off + 3 * j + 1] = make_float2(c2, s2);
        tw[off + 3 * j + 2] = make_float2(c3, s3);
    }
}

__device__ __forceinline__ void rad4(float2 b0, float2 b1, float2 b2, float2 b3,
                                     float2& y0, float2& y1, float2& y2, float2& y3)
{
    float2 t0 = make_float2(b0.x + b2.x, b0.y + b2.y);
    float2 t1 = make_float2(b0.x - b2.x, b0.y - b2.y);
    float2 t2 = make_float2(b1.x + b3.x, b1.y + b3.y);
    float2 t3 = make_float2(-(b1.y - b3.y), b1.x - b3.x);   // +i*(b1-b3)
    y0 = make_float2(t0.x + t2.x, t0.y + t2.y);
    y1 = make_float2(t1.x + t3.x, t1.y + t3.y);
    y2 = make_float2(t0.x - t2.x, t0.y - t2.y);
    y3 = make_float2(t1.x - t3.x, t1.y - t3.y);
}

template<int S, int OFF>
__device__ __forceinline__ void stage4(float2* x, const float2* tw, int bi0)
{
    const int sh = 2 * S;
    const int quarter = 1 << sh;
    #pragma unroll
    for (int u = 0; u < 4; u++) {
        const int bi = bi0 + (u << 6);
        const int j  = bi & (quarter - 1);
        const int base = ((bi >> sh) << (sh + 2)) | j;
        float2 b0 = x[base];
        float2 b1 = x[base + quarter];
        float2 b2 = x[base + 2 * quarter];
        float2 b3 = x[base + 3 * quarter];
        b1 = cmul(b1, tw[OFF + 3 * j + 0]);
        b2 = cmul(b2, tw[OFF + 3 * j + 1]);
        b3 = cmul(b3, tw[OFF + 3 * j + 2]);
        float2 y0, y1, y2, y3;
        rad4(b0, b1, b2, b3, y0, y1, y2, y3);
        x[base]               = y0;
        x[base + quarter]     = y1;
        x[base + 2 * quarter] = y2;
        x[base + 3 * quarter] = y3;
    }
}

// Final stage (S=4), pruned to the fftshift+crop-surviving halves.
__device__ __forceinline__ void stage4_last_pruned(float2* x, const float2* tw,
                                                   int bi0)
{
    const int quarter = 256;
    #pragma unroll
    for (int u = 0; u < 4; u++) {
        const int j = bi0 + (u << 6);          // base == j for S=4
        float2 b0 = x[j];
        float2 b1 = cmul(x[j + quarter],     tw[TW_OFF4 + 3 * j + 0]);
        float2 b2 = cmul(x[j + 2 * quarter], tw[TW_OFF4 + 3 * j + 1]);
        float2 b3 = cmul(x[j + 3 * quarter], tw[TW_OFF4 + 3 * j + 2]);
        float2 t0 = make_float2(b0.x + b2.x, b0.y + b2.y);
        float2 t1 = make_float2(b0.x - b2.x, b0.y - b2.y);
        float2 t2 = make_float2(b1.x + b3.x, b1.y + b3.y);
        float2 t3 = make_float2(-(b1.y - b3.y), b1.x - b3.x);
        x[j]               = make_float2(t0.x + t2.x, t0.y + t2.y);  // y0
        x[j + 3 * quarter] = make_float2(t1.x - t3.x, t1.y - t3.y);  // y3
    }
}

__device__ __forceinline__ void fft8x1024(float2* data, const float2* tw, int tid)
{
    {   // stage 0: float4-vectorized, twiddle-free, fft-major
        float4* xv = reinterpret_cast<float4*>(data + (tid & 7) * PITCH);
        const int bi0 = tid >> 3;
        #pragma unroll
        for (int u = 0; u < 4; u++) {
            const int bi = bi0 + (u << 6);
            float4 f01 = xv[2 * bi];
            float4 f23 = xv[2 * bi + 1];
            float2 y0, y1, y2, y3;
            rad4(make_float2(f01.x, f01.y), make_float2(f01.z, f01.w),
                 make_float2(f23.x, f23.y), make_float2(f23.z, f23.w),
                 y0, y1, y2, y3);
            xv[2 * bi]     = make_float4(y0.x, y0.y, y1.x, y1.y);
            xv[2 * bi + 1] = make_float4(y2.x, y2.y, y3.x, y3.y);
        }
        __syncthreads();
    }
    stage4<1, TW_OFF1>(data + (tid & 7) * PITCH, tw, tid >> 3);
    __syncthreads();
    stage4<2, TW_OFF2>(data + (tid >> 6) * PITCH, tw, tid & 63);
    __syncthreads();
    stage4<3, TW_OFF3>(data + (tid >> 6) * PITCH, tw, tid & 63);
    __syncthreads();
    stage4_last_pruned(data + (tid >> 6) * PITCH, tw, tid & 63);
    __syncthreads();
}

// ---------------------------------------------------------------------------
// FFT along kx on the packed grid. Block = ky pair -> 8 (ky,p) columns.
// 512 blocks. Pruned output rows [0,256) U [768,1024).
// ---------------------------------------------------------------------------
__global__ __launch_bounds__(512, 3)
void fft_x_kernel()
{
    extern __shared__ float2 sm[];
    float2* tw   = sm;
    float2* data = sm + TW_TOT;
    const int tid = threadIdx.x;
    init_tw(tw, tid, 512);

    const int ky0 = blockIdx.x * 2;

    for (int t = tid; t < 8 * KGRID; t += 512) {
        int ix = t >> 3;
        int r  = t & 7;                        // r = kyl*4 + p
        data[r * PITCH + digit_rev10(ix)] =
            g_grid[(ix * KGRID + ky0 + (r >> 2)) * NPACK + (r & 3)];
    }
    __syncthreads();

    fft8x1024(data, tw, tid);

    for (int t = tid; t < 8 * 512; t += 512) {
        int xl = t >> 3;
        int r  = t & 7;
        int xg = (xl < 256) ? xl : xl + 512;   // rows kept after shift+crop
        g_grid[(xg * KGRID + ky0 + (r >> 2)) * NPACK + (r & 3)] =
            data[r * PITCH + xg];
    }
}

// ---------------------------------------------------------------------------
__device__ __forceinline__ float inv_apod(int i)
{
    float xv = ((float)i - 256.0f) * (1.0f / 1024.0f);
    float pj = PI_F * 6.0f * xv;
    float tv = BETA_F * BETA_F - pj * pj;
    float st = sqrtf(fabsf(tv));
    float num = (tv > 0.0f) ? sinhf(st) : sinf(st);
    return fmaxf(st, 1e-6f) / num;
}

// FFT along ky on packed data: 2 x rows x 4 packed FFTs per block; 256 blocks.
// Epilogue: batch 2p = Re, batch 2p+1 = Im, with fftshift/crop/deapod.
__global__ __launch_bounds__(512, 3)
void fft_y_kernel(float* __restrict__ out)
{
    extern __shared__ float2 sm[];
    float2* tw   = sm;
    float2* data = sm + TW_TOT;
    const int tid = threadIdx.x;
    init_tw(tw, tid, 512);

    const int x_img0 = blockIdx.x * 2;

    for (int t = tid; t < 8 * KGRID; t += 512) {
        int ky = t >> 3;
        int r  = t & 7;                        // r = xl*4 + p
        int xl = r >> 2;
        int p  = r & 3;
        int x_src = ((x_img0 + xl) + 768) & (KGRID - 1);
        data[r * PITCH + digit_rev10(ky)] =
            g_grid[(x_src * KGRID + ky) * NPACK + p];
    }
    __syncthreads();

    fft8x1024(data, tw, tid);

    const float iax0 = inv_apod(x_img0);
    const float iax1 = inv_apod(x_img0 + 1);
    for (int t = tid; t < 8 * NIMG; t += 512) {
        int r  = t >> 9;                       // 0..7 = xl*4 + p
        int yi = t & 511;
        int xl = r >> 2;
        int p  = r & 3;
        int ys = (yi + 768) & (KGRID - 1);     // in [0,256) U [768,1024)
        float2 v = data[r * PITCH + ys];
        float scale = (xl ? iax1 : iax0) * inv_apod(yi);
        int xi = x_img0 + xl;
        out[(2 * p)     * (NIMG * NIMG) + xi * NIMG + yi] = v.x * scale;
        out[(2 * p + 1) * (NIMG * NIMG) + xi * NIMG + yi] = v.y * scale;
    }
}

// ---------------------------------------------------------------------------
extern "C" void kernel_launch(void* const* d_in, const int* in_sizes, int n_in,
                              void* d_out, int out_size)
{
    const float* yr  = (const float*)d_in[0];
    const float* yi  = (const float*)d_in[1];
    const float* uv  = (const float*)d_in[2];
    const float* wts = (const float*)d_in[3];
    float* out = (float*)d_out;

    const int smem_fft = (TW_TOT + 8 * PITCH) * (int)sizeof(float2); // ~73.8 KB
    cudaFuncSetAttribute(fft_x_kernel,
                         cudaFuncAttributeMaxDynamicSharedMemorySize, smem_fft);
    cudaFuncSetAttribute(fft_y_kernel,
                         cudaFuncAttributeMaxDynamicSharedMemorySize, smem_fft);

    zero_kernel<<<2048, 256>>>();
    scatter_kernel<<<(8 * MPTS + 255) / 256, 256>>>(yr, yi, uv, wts);
    fft_x_kernel<<<KGRID / 2, 512, smem_fft>>>();
    fft_y_kernel<<<NIMG / 2, 512, smem_fft>>>(out);
}

// round 11
// speedup vs baseline: 1.0580x; 1.0580x over previous
#include <cuda_runtime.h>
#include <math.h>

// ---------------------------------------------------------------------------
// NUFFT adjoint (Kaiser-Bessel gridding) for GB300 — round 11
// = R10 (Hermitian-packed 32MB grid: scatter writes C_p = He(G_2p)+i He(G_2p+1)
//   at +k and -k; fft_x reads the packed grid once; fft_y Re/Im-splits)
// + FIX: scatter lane order. v (packed-pair half) now lives in lane bit 0 so
//   adjacent lanes write the two contiguous 16B halves of each 32B cell and
//   the LSU merges them (R10 had sign s in bit 0 -> no merging -> 4x LTS
//   transactions -> scatter 72->116us).
// ---------------------------------------------------------------------------

#define KGRID   1024
#define NIMG    512
#define MPTS    200000
#define JW      6
#define BETA_F  14.04f
#define PI_F    3.14159265358979f

#define NPACK   4                         // packed batch pairs per cell
#define GRID_F2 (KGRID * KGRID * NPACK)   // 4M float2 = 32 MB
#define PITCH   1026                      // smem row pitch (float2), even

#define TW_OFF1 0
#define TW_OFF2 12
#define TW_OFF3 60
#define TW_OFF4 252
#define TW_TOT  1020

__device__ float2 g_grid[GRID_F2];

// ---------------------------------------------------------------------------
__device__ __forceinline__ float bessel_i0(float x)
{
    if (x < 3.75f) {
        float t = x * (1.0f / 3.75f);
        t *= t;
        return 1.0f + t * (3.5156229f + t * (3.0899424f + t * (1.2067492f +
                     t * (0.2659732f + t * (0.0360768f + t * 0.0045813f)))));
    } else {
        float t = 3.75f / x;
        float p = 0.39894228f + t * (0.01328592f + t * (0.00225319f +
                  t * (-0.00157565f + t * (0.00916281f + t * (-0.02057706f +
                  t * (0.02635537f + t * (-0.01647633f + t * 0.00392377f)))))));
        return __expf(x) * rsqrtf(x) * p;
    }
}

// ---------------------------------------------------------------------------
// Zero the packed grid (32 MB). Also the L2 warm for the scatter's atomics.
// ---------------------------------------------------------------------------
__global__ void zero_kernel()
{
    float4* p = reinterpret_cast<float4*>(g_grid);
    const int n = GRID_F2 / 2;
    for (int i = blockIdx.x * blockDim.x + threadIdx.x; i < n;
         i += gridDim.x * blockDim.x)
        p[i] = make_float4(0.f, 0.f, 0.f, 0.f);
}

// ---------------------------------------------------------------------------
// Hermitian-packed gridding scatter: 8 threads per measurement.
//   lane bit0: v = packed pair half (p=2v,2v+1)  -> adjacent-lane coalescing
//   lane bit1: h = x-tap half
//   lane bit2: s = cell sign (+k / -k conjugate)
// 18 red.v4.f32 per thread.
// ---------------------------------------------------------------------------
__global__ __launch_bounds__(256)
void scatter_kernel(const float* __restrict__ yr, const float* __restrict__ yi,
                    const float* __restrict__ uv, const float* __restrict__ wts)
{
    const int gid = blockIdx.x * blockDim.x + threadIdx.x;
    const int m = gid >> 3;
    const int u = gid & 7;
    const int v = u & 1;                   // packed p in {2v, 2v+1}
    const int h = (u >> 1) & 1;            // a in {3h, 3h+1, 3h+2}
    const int s = (u >> 2) & 1;            // 0: +k, 1: -k (conjugate)
    if (m >= MPTS) return;

    const float2 c2 = reinterpret_cast<const float2*>(uv)[m];
    const float inv_i0b = 1.0f / bessel_i0(BETA_F);

    int ixv[3], iyv[JW];
    float wx[3], wy[JW];

    {   // axis 0: this thread's 3 taps (mirrored for s=1)
        float k  = c2.x / (2.0f * PI_F) * (float)KGRID;
        float km = floorf(k - 3.0f);
        #pragma unroll
        for (int j = 0; j < 3; j++) {
            int jj = 3 * h + j;
            float pt = km + (float)(jj + 1);
            float d  = k - pt;
            float arg = fmaxf(1.0f - d * d * (1.0f / 9.0f), 0.0f);
            wx[j] = bessel_i0(BETA_F * sqrtf(arg)) * inv_i0b;
            int idx = ((int)pt + KGRID) & (KGRID - 1);
            ixv[j] = s ? ((KGRID - idx) & (KGRID - 1)) : idx;
        }
    }
    {   // axis 1: all 6 taps (mirrored for s=1)
        float k  = c2.y / (2.0f * PI_F) * (float)KGRID;
        float km = floorf(k - 3.0f);
        #pragma unroll
        for (int j = 0; j < JW; j++) {
            float pt = km + (float)(j + 1);
            float d  = k - pt;
            float arg = fmaxf(1.0f - d * d * (1.0f / 9.0f), 0.0f);
            wy[j] = bessel_i0(BETA_F * sqrtf(arg)) * inv_i0b;
            int idx = ((int)pt + KGRID) & (KGRID - 1);
            iyv[j] = s ? ((KGRID - idx) & (KGRID - 1)) : idx;
        }
    }

    // batches 4v..4v+3 -> packed values p=2v and 2v+1; 0.5 of He in wt2.
    const int b0 = 4 * v;
    const float wt2 = 0.5f * wts[m];
    const float yr0 = yr[(b0 + 0) * MPTS + m], yi0 = yi[(b0 + 0) * MPTS + m];
    const float yr1 = yr[(b0 + 1) * MPTS + m], yi1 = yi[(b0 + 1) * MPTS + m];
    const float yr2 = yr[(b0 + 2) * MPTS + m], yi2 = yi[(b0 + 2) * MPTS + m];
    const float yr3 = yr[(b0 + 3) * MPTS + m], yi3 = yi[(b0 + 3) * MPTS + m];

    const float sgn = s ? -1.0f : 1.0f;
    const float cra = wt2 * (yr0 - sgn * yi1);
    const float cia = wt2 * (sgn * yi0 + yr1);
    const float crb = wt2 * (yr2 - sgn * yi3);
    const float cib = wt2 * (sgn * yi2 + yr3);

    #pragma unroll
    for (int a = 0; a < 3; a++) {
        const int rowbase = ixv[a] * KGRID;
        const float wxa = wx[a];
        #pragma unroll
        for (int c = 0; c < JW; c++) {
            const float w2 = wxa * wy[c];
            float* fp = reinterpret_cast<float*>(
                            &g_grid[(rowbase + iyv[c]) * NPACK]) + 4 * v;
            asm volatile(
                "red.global.add.v4.f32 [%0], {%1, %2, %3, %4};"
                :: "l"(fp),
                   "f"(w2 * cra), "f"(w2 * cia),
                   "f"(w2 * crb), "f"(w2 * cib)
                : "memory");
        }
    }
}

// ---------------------------------------------------------------------------
// Radix-4 FFT machinery (inverse, e^{+i})
// ---------------------------------------------------------------------------
__device__ __forceinline__ int digit_rev10(int i)
{
    int r = (int)(__brev((unsigned)i) >> 22);
    return ((r & 0x155) << 1) | ((r & 0x2AA) >> 1);
}

__device__ __forceinline__ float2 cmul(float2 a, float2 b)
{
    return make_float2(a.x * b.x - a.y * b.y, a.x * b.y + a.y * b.x);
}

__device__ __forceinline__ void init_tw(float2* tw, int tid, int nthr)
{
    for (int t = tid; t < 340; t += nthr) {
        int s, j, off;
        if      (t < 4)  { s = 1; j = t;      off = TW_OFF1; }
        else if (t < 20) { s = 2; j = t - 4;  off = TW_OFF2; }
        else if (t < 84) { s = 3; j = t - 20; off = TW_OFF3; }
        else             { s = 4; j = t - 84; off = TW_OFF4; }
        int em = j << (8 - 2 * s);
        float a = (float)em * (2.0f * PI_F / 1024.0f);
        float s1, c1, s2, c2, s3, c3;
        __sincosf(a, &s1, &c1);
        __sincosf(2.0f * a, &s2, &c2);
        __sincosf(3.0f * a, &s3, &c3);
        tw[off + 3 * j + 0] = make_float2(c1, s1);
        tw[off + 3 * j + 1] = make_float2(c2, s2);
        tw[off + 3 * j + 2] = make_float2(c3, s3);
    }
}

__device__ __forceinline__ void rad4(float2 b0, float2 b1, float2 b2, float2 b3,
                                     float2& y0, float2& y1, float2& y2, float2& y3)
{
    float2 t0 = make_float2(b0.x + b2.x, b0.y + b2.y);
    float2 t1 = make_float2(b0.x - b2.x, b0.y - b2.y);
    float2 t2 = make_float2(b1.x + b3.x, b1.y + b3.y);
    float2 t3 = make_float2(-(b1.y - b3.y), b1.x - b3.x);   // +i*(b1-b3)
    y0 = make_float2(t0.x + t2.x, t0.y + t2.y);
    y1 = make_float2(t1.x + t3.x, t1.y + t3.y);
    y2 = make_float2(t0.x - t2.x, t0.y - t2.y);
    y3 = make_float2(t1.x - t3.x, t1.y - t3.y);
}

template<int S, int OFF>
__device__ __forceinline__ void stage4(float2* x, const float2* tw, int bi0)
{
    const int sh = 2 * S;
    const int quarter = 1 << sh;
    #pragma unroll
    for (int u = 0; u < 4; u++) {
        const int bi = bi0 + (u << 6);
        const int j  = bi & (quarter - 1);
        const int base = ((bi >> sh) << (sh + 2)) | j;
        float2 b0 = x[base];
        float2 b1 = x[base + quarter];
        float2 b2 = x[base + 2 * quarter];
        float2 b3 = x[base + 3 * quarter];
        b1 = cmul(b1, tw[OFF + 3 * j + 0]);
        b2 = cmul(b2, tw[OFF + 3 * j + 1]);
        b3 = cmul(b3, tw[OFF + 3 * j + 2]);
        float2 y0, y1, y2, y3;
        rad4(b0, b1, b2, b3, y0, y1, y2, y3);
        x[base]               = y0;
        x[base + quarter]     = y1;
        x[base + 2 * quarter] = y2;
        x[base + 3 * quarter] = y3;
    }
}

// Final stage (S=4), pruned to the fftshift+crop-surviving halves.
__device__ __forceinline__ void stage4_last_pruned(float2* x, const float2* tw,
                                                   int bi0)
{
    const int quarter = 256;
    #pragma unroll
    for (int u = 0; u < 4; u++) {
        const int j = bi0 + (u << 6);          // base == j for S=4
        float2 b0 = x[j];
        float2 b1 = cmul(x[j + quarter],     tw[TW_OFF4 + 3 * j + 0]);
        float2 b2 = cmul(x[j + 2 * quarter], tw[TW_OFF4 + 3 * j + 1]);
        float2 b3 = cmul(x[j + 3 * quarter], tw[TW_OFF4 + 3 * j + 2]);
        float2 t0 = make_float2(b0.x + b2.x, b0.y + b2.y);
        float2 t1 = make_float2(b0.x - b2.x, b0.y - b2.y);
        float2 t2 = make_float2(b1.x + b3.x, b1.y + b3.y);
        float2 t3 = make_float2(-(b1.y - b3.y), b1.x - b3.x);
        x[j]               = make_float2(t0.x + t2.x, t0.y + t2.y);  // y0
        x[j + 3 * quarter] = make_float2(t1.x - t3.x, t1.y - t3.y);  // y3
    }
}

__device__ __forceinline__ void fft8x1024(float2* data, const float2* tw, int tid)
{
    {   // stage 0: float4-vectorized, twiddle-free, fft-major
        float4* xv = reinterpret_cast<float4*>(data + (tid & 7) * PITCH);
        const int bi0 = tid >> 3;
        #pragma unroll
        for (int u = 0; u < 4; u++) {
            const int bi = bi0 + (u << 6);
            float4 f01 = xv[2 * bi];
            float4 f23 = xv[2 * bi + 1];
            float2 y0, y1, y2, y3;
            rad4(make_float2(f01.x, f01.y), make_float2(f01.z, f01.w),
                 make_float2(f23.x, f23.y), make_float2(f23.z, f23.w),
                 y0, y1, y2, y3);
            xv[2 * bi]     = make_float4(y0.x, y0.y, y1.x, y1.y);
            xv[2 * bi + 1] = make_float4(y2.x, y2.y, y3.x, y3.y);
        }
        __syncthreads();
    }
    stage4<1, TW_OFF1>(data + (tid & 7) * PITCH, tw, tid >> 3);
    __syncthreads();
    stage4<2, TW_OFF2>(data + (tid >> 6) * PITCH, tw, tid & 63);
    __syncthreads();
    stage4<3, TW_OFF3>(data + (tid >> 6) * PITCH, tw, tid & 63);
    __syncthreads();
    stage4_last_pruned(data + (tid >> 6) * PITCH, tw, tid & 63);
    __syncthreads();
}

// ---------------------------------------------------------------------------
// FFT along kx on the packed grid. Block = ky pair -> 8 (ky,p) columns.
// 512 blocks. Pruned output rows [0,256) U [768,1024).
// ---------------------------------------------------------------------------
__global__ __launch_bounds__(512, 3)
void fft_x_kernel()
{
    extern __shared__ float2 sm[];
    float2* tw   = sm;
    float2* data = sm + TW_TOT;
    const int tid = threadIdx.x;
    init_tw(tw, tid, 512);

    const int ky0 = blockIdx.x * 2;

    for (int t = tid; t < 8 * KGRID; t += 512) {
        int ix = t >> 3;
        int r  = t & 7;                        // r = kyl*4 + p
        data[r * PITCH + digit_rev10(ix)] =
            g_grid[(ix * KGRID + ky0 + (r >> 2)) * NPACK + (r & 3)];
    }
    __syncthreads();

    fft8x1024(data, tw, tid);

    for (int t = tid; t < 8 * 512; t += 512) {
        int xl = t >> 3;
        int r  = t & 7;
        int xg = (xl < 256) ? xl : xl + 512;   // rows kept after shift+crop
        g_grid[(xg * KGRID + ky0 + (r >> 2)) * NPACK + (r & 3)] =
            data[r * PITCH + xg];
    }
}

// ---------------------------------------------------------------------------
__device__ __forceinline__ float inv_apod(int i)
{
    float xv = ((float)i - 256.0f) * (1.0f / 1024.0f);
    float pj = PI_F * 6.0f * xv;
    float tv = BETA_F * BETA_F - pj * pj;
    float st = sqrtf(fabsf(tv));
    float num = (tv > 0.0f) ? sinhf(st) : sinf(st);
    return fmaxf(st, 1e-6f) / num;
}

// FFT along ky on packed data: 2 x rows x 4 packed FFTs per block; 256 blocks.
// Epilogue: batch 2p = Re, batch 2p+1 = Im, with fftshift/crop/deapod.
__global__ __launch_bounds__(512, 3)
void fft_y_kernel(float* __restrict__ out)
{
    extern __shared__ float2 sm[];
    float2* tw   = sm;
    float2* data = sm + TW_TOT;
    const int tid = threadIdx.x;
    init_tw(tw, tid, 512);

    const int x_img0 = blockIdx.x * 2;

    for (int t = tid; t < 8 * KGRID; t += 512) {
        int ky = t >> 3;
        int r  = t & 7;                        // r = xl*4 + p
        int xl = r >> 2;
        int p  = r & 3;
        int x_src = ((x_img0 + xl) + 768) & (KGRID - 1);
        data[r * PITCH + digit_rev10(ky)] =
            g_grid[(x_src * KGRID + ky) * NPACK + p];
    }
    __syncthreads();

    fft8x1024(data, tw, tid);

    const float iax0 = inv_apod(x_img0);
    const float iax1 = inv_apod(x_img0 + 1);
    for (int t = tid; t < 8 * NIMG; t += 512) {
        int r  = t >> 9;                       // 0..7 = xl*4 + p
        int yi = t & 511;
        int xl = r >> 2;
        int p  = r & 3;
        int ys = (yi + 768) & (KGRID - 1);     // in [0,256) U [768,1024)
        float2 v = data[r * PITCH + ys];
        float scale = (xl ? iax1 : iax0) * inv_apod(yi);
        int xi = x_img0 + xl;
        out[(2 * p)     * (NIMG * NIMG) + xi * NIMG + yi] = v.x * scale;
        out[(2 * p + 1) * (NIMG * NIMG) + xi * NIMG + yi] = v.y * scale;
    }
}

// ---------------------------------------------------------------------------
extern "C" void kernel_launch(void* const* d_in, const int* in_sizes, int n_in,
                              void* d_out, int out_size)
{
    const float* yr  = (const float*)d_in[0];
    const float* yi  = (const float*)d_in[1];
    const float* uv  = (const float*)d_in[2];
    const float* wts = (const float*)d_in[3];
    float* out = (float*)d_out;

    const int smem_fft = (TW_TOT + 8 * PITCH) * (int)sizeof(float2); // ~73.8 KB
    cudaFuncSetAttribute(fft_x_kernel,
                         cudaFuncAttributeMaxDynamicSharedMemorySize, smem_fft);
    cudaFuncSetAttribute(fft_y_kernel,
                         cudaFuncAttributeMaxDynamicSharedMemorySize, smem_fft);

    zero_kernel<<<2048, 256>>>();
    scatter_kernel<<<(8 * MPTS + 255) / 256, 256>>>(yr, yi, uv, wts);
    fft_x_kernel<<<KGRID / 2, 512, smem_fft>>>();
    fft_y_kernel<<<NIMG / 2, 512, smem_fft>>>(out);
}

// round 13
// speedup vs baseline: 1.1412x; 1.0786x over previous
#include <cuda_runtime.h>
#include <math.h>

// ---------------------------------------------------------------------------
// NUFFT adjoint (Kaiser-Bessel gridding) for GB300 — round 13
// = R12 (256-thread / 4-FFT blocks for occupancy) but RACE-FREE:
//   fft_x writes its packed output to a disjoint buffer g_fx (g_grid is
//   read-only during fft_x, so splitting the (iy,-iy) column pair across
//   two blocks is now safe). R12 had blocks writing g_grid columns that
//   other blocks were concurrently mirror-reading -> rel_err 0.18.
// Scatter/zero = R9's proven versions (64MB grid, q/h 8-way split).
// ---------------------------------------------------------------------------

#define KGRID   1024
#define NIMG    512
#define MPTS    200000
#define BATCH   8
#define JW      6
#define BETA_F  14.04f
#define PI_F    3.14159265358979f

#define GRID_F2 (KGRID * KGRID * BATCH)   // 64 MB
#define FX_F2   (NIMG * KGRID * 4)        // 16 MB packed fft_x output
#define PITCH   1028                      // smem row pitch (float2)

#define TW_OFF1 0
#define TW_OFF2 12
#define TW_OFF3 60
#define TW_OFF4 252
#define TW_TOT  1020

__device__ float2 g_grid[GRID_F2];
__device__ float2 g_fx[FX_F2];            // [xl][ky][p], xl = compacted row

// ---------------------------------------------------------------------------
__device__ __forceinline__ float bessel_i0(float x)
{
    if (x < 3.75f) {
        float t = x * (1.0f / 3.75f);
        t *= t;
        return 1.0f + t * (3.5156229f + t * (3.0899424f + t * (1.2067492f +
                     t * (0.2659732f + t * (0.0360768f + t * 0.0045813f)))));
    } else {
        float t = 3.75f / x;
        float p = 0.39894228f + t * (0.01328592f + t * (0.00225319f +
                  t * (-0.00157565f + t * (0.00916281f + t * (-0.02057706f +
                  t * (0.02635537f + t * (-0.01647633f + t * 0.00392377f)))))));
        return __expf(x) * rsqrtf(x) * p;
    }
}

// ---------------------------------------------------------------------------
// Zero the grid (64 MB). Also the L2 warm for the scatter's atomics.
// ---------------------------------------------------------------------------
__global__ void zero_kernel()
{
    float4* p = reinterpret_cast<float4*>(g_grid);
    const int n = GRID_F2 / 2;
    for (int i = blockIdx.x * blockDim.x + threadIdx.x; i < n;
         i += gridDim.x * blockDim.x)
        p[i] = make_float4(0.f, 0.f, 0.f, 0.f);
}

// ---------------------------------------------------------------------------
// Gridding scatter (R9): 8 threads per measurement; q = batch pair (lanes
// 0-3 write 4 contiguous 16B quarters of each 64B cell), h = x-tap half.
// ---------------------------------------------------------------------------
__global__ __launch_bounds__(256)
void scatter_kernel(const float* __restrict__ yr, const float* __restrict__ yi,
                    const float* __restrict__ uv, const float* __restrict__ wts)
{
    const int gid = blockIdx.x * blockDim.x + threadIdx.x;
    const int m = gid >> 3;
    const int q = gid & 3;                 // batches 2q, 2q+1
    const int h = (gid >> 2) & 1;          // a in {3h, 3h+1, 3h+2}
    if (m >= MPTS) return;

    const float2 c2 = reinterpret_cast<const float2*>(uv)[m];
    const float wt = wts[m];
    const float inv_i0b = 1.0f / bessel_i0(BETA_F);

    int ixv[3], iyv[JW];
    float wx[3], wy[JW];

    {
        float k  = c2.x / (2.0f * PI_F) * (float)KGRID;
        float km = floorf(k - 3.0f);
        #pragma unroll
        for (int j = 0; j < 3; j++) {
            int jj = 3 * h + j;
            float pt = km + (float)(jj + 1);
            float d  = k - pt;
            float arg = fmaxf(1.0f - d * d * (1.0f / 9.0f), 0.0f);
            wx[j] = bessel_i0(BETA_F * sqrtf(arg)) * inv_i0b;
            ixv[j] = ((int)pt + KGRID) & (KGRID - 1);
        }
    }
    {
        float k  = c2.y / (2.0f * PI_F) * (float)KGRID;
        float km = floorf(k - 3.0f);
        #pragma unroll
        for (int j = 0; j < JW; j++) {
            float pt = km + (float)(j + 1);
            float d  = k - pt;
            float arg = fmaxf(1.0f - d * d * (1.0f / 9.0f), 0.0f);
            wy[j] = bessel_i0(BETA_F * sqrtf(arg)) * inv_i0b;
            iyv[j] = ((int)pt + KGRID) & (KGRID - 1);
        }
    }

    const int b0 = 2 * q;
    const float yr0 = yr[b0 * MPTS + m] * wt;
    const float yi0 = yi[b0 * MPTS + m] * wt;
    const float yr1 = yr[(b0 + 1) * MPTS + m] * wt;
    const float yi1 = yi[(b0 + 1) * MPTS + m] * wt;

    #pragma unroll
    for (int a = 0; a < 3; a++) {
        const int rowbase = ixv[a] * KGRID;
        const float wxa = wx[a];
        #pragma unroll
        for (int c = 0; c < JW; c++) {
            const float w2 = wxa * wy[c];
            float* fp = reinterpret_cast<float*>(&g_grid[(rowbase + iyv[c]) * BATCH])
                        + 4 * q;
            asm volatile(
                "red.global.add.v4.f32 [%0], {%1, %2, %3, %4};"
                :: "l"(fp),
                   "f"(w2 * yr0), "f"(w2 * yi0),
                   "f"(w2 * yr1), "f"(w2 * yi1)
                : "memory");
        }
    }
}

// ---------------------------------------------------------------------------
// Radix-4 FFT machinery (inverse, e^{+i})
// ---------------------------------------------------------------------------
__device__ __forceinline__ int digit_rev10(int i)
{
    int r = (int)(__brev((unsigned)i) >> 22);
    return ((r & 0x155) << 1) | ((r & 0x2AA) >> 1);
}

__device__ __forceinline__ float2 cmul(float2 a, float2 b)
{
    return make_float2(a.x * b.x - a.y * b.y, a.x * b.y + a.y * b.x);
}

__device__ __forceinline__ void init_tw(float2* tw, int tid, int nthr)
{
    for (int t = tid; t < 340; t += nthr) {
        int s, j, off;
        if      (t < 4)  { s = 1; j = t;      off = TW_OFF1; }
        else if (t < 20) { s = 2; j = t - 4;  off = TW_OFF2; }
        else if (t < 84) { s = 3; j = t - 20; off = TW_OFF3; }
        else             { s = 4; j = t - 84; off = TW_OFF4; }
        int em = j << (8 - 2 * s);
        float a = (float)em * (2.0f * PI_F / 1024.0f);
        float s1, c1, s2, c2, s3, c3;
        __sincosf(a, &s1, &c1);
        __sincosf(2.0f * a, &s2, &c2);
        __sincosf(3.0f * a, &s3, &c3);
        tw[off + 3 * j + 0] = make_float2(c1, s1);
        tw[off + 3 * j + 1] = make_float2(c2, s2);
        tw[off + 3 * j + 2] = make_float2(c3, s3);
    }
}

__device__ __forceinline__ void rad4(float2 b0, float2 b1, float2 b2, float2 b3,
                                     float2& y0, float2& y1, float2& y2, float2& y3)
{
    float2 t0 = make_float2(b0.x + b2.x, b0.y + b2.y);
    float2 t1 = make_float2(b0.x - b2.x, b0.y - b2.y);
    float2 t2 = make_float2(b1.x + b3.x, b1.y + b3.y);
    float2 t3 = make_float2(-(b1.y - b3.y), b1.x - b3.x);   // +i*(b1-b3)
    y0 = make_float2(t0.x + t2.x, t0.y + t2.y);
    y1 = make_float2(t1.x + t3.x, t1.y + t3.y);
    y2 = make_float2(t0.x - t2.x, t0.y - t2.y);
    y3 = make_float2(t1.x - t3.x, t1.y - t3.y);
}

template<int S, int OFF>
__device__ __forceinline__ void stage4(float2* x, const float2* tw, int bi0)
{
    const int sh = 2 * S;
    const int quarter = 1 << sh;
    #pragma unroll
    for (int u = 0; u < 4; u++) {
        const int bi = bi0 + (u << 6);
        const int j  = bi & (quarter - 1);
        const int base = ((bi >> sh) << (sh + 2)) | j;
        float2 b0 = x[base];
        float2 b1 = x[base + quarter];
        float2 b2 = x[base + 2 * quarter];
        float2 b3 = x[base + 3 * quarter];
        b1 = cmul(b1, tw[OFF + 3 * j + 0]);
        b2 = cmul(b2, tw[OFF + 3 * j + 1]);
        b3 = cmul(b3, tw[OFF + 3 * j + 2]);
        float2 y0, y1, y2, y3;
        rad4(b0, b1, b2, b3, y0, y1, y2, y3);
        x[base]               = y0;
        x[base + quarter]     = y1;
        x[base + 2 * quarter] = y2;
        x[base + 3 * quarter] = y3;
    }
}

// Final stage (S=4), pruned to the fftshift+crop-surviving halves.
__device__ __forceinline__ void stage4_last_pruned(float2* x, const float2* tw,
                                                   int bi0)
{
    const int quarter = 256;
    #pragma unroll
    for (int u = 0; u < 4; u++) {
        const int j = bi0 + (u << 6);          // base == j for S=4
        float2 b0 = x[j];
        float2 b1 = cmul(x[j + quarter],     tw[TW_OFF4 + 3 * j + 0]);
        float2 b2 = cmul(x[j + 2 * quarter], tw[TW_OFF4 + 3 * j + 1]);
        float2 b3 = cmul(x[j + 3 * quarter], tw[TW_OFF4 + 3 * j + 2]);
        float2 t0 = make_float2(b0.x + b2.x, b0.y + b2.y);
        float2 t1 = make_float2(b0.x - b2.x, b0.y - b2.y);
        float2 t2 = make_float2(b1.x + b3.x, b1.y + b3.y);
        float2 t3 = make_float2(-(b1.y - b3.y), b1.x - b3.x);
        x[j]               = make_float2(t0.x + t2.x, t0.y + t2.y);  // y0
        x[j + 3 * quarter] = make_float2(t1.x - t3.x, t1.y - t3.y);  // y3
    }
}

// 4 independent 1024-pt inverse FFTs; 256 threads; rows pitch PITCH.
__device__ __forceinline__ void fft4x1024(float2* data, const float2* tw, int tid)
{
    {   // stage 0: element-major float4 (row warp-constant)
        float4* xv = reinterpret_cast<float4*>(data + (tid >> 6) * PITCH);
        const int bi0 = tid & 63;
        #pragma unroll
        for (int u = 0; u < 4; u++) {
            const int bi = bi0 + (u << 6);
            float4 f01 = xv[2 * bi];
            float4 f23 = xv[2 * bi + 1];
            float2 y0, y1, y2, y3;
            rad4(make_float2(f01.x, f01.y), make_float2(f01.z, f01.w),
                 make_float2(f23.x, f23.y), make_float2(f23.z, f23.w),
                 y0, y1, y2, y3);
            xv[2 * bi]     = make_float4(y0.x, y0.y, y1.x, y1.y);
            xv[2 * bi + 1] = make_float4(y2.x, y2.y, y3.x, y3.y);
        }
        __syncthreads();
    }
    stage4<1, TW_OFF1>(data + (tid & 3) * PITCH, tw, tid >> 2);
    __syncthreads();
    stage4<2, TW_OFF2>(data + (tid >> 6) * PITCH, tw, tid & 63);
    __syncthreads();
    stage4<3, TW_OFF3>(data + (tid >> 6) * PITCH, tw, tid & 63);
    __syncthreads();
    stage4_last_pruned(data + (tid >> 6) * PITCH, tw, tid & 63);
    __syncthreads();
}

// ---------------------------------------------------------------------------
// FFT along kx on Hermitian-packed batch pairs. Block b: iy = b>>1,
// half = b&1 -> output column colA; 4 packed FFTs; 1026 blocks.
// Reads g_grid (read-only here); writes packed/compacted rows to g_fx.
// ---------------------------------------------------------------------------
__global__ __launch_bounds__(256, 5)
void fft_x_kernel()
{
    extern __shared__ float2 sm[];
    float2* tw   = sm;
    float2* data = sm + TW_TOT;
    const int tid = threadIdx.x;
    init_tw(tw, tid, 256);

    const int iy   = blockIdx.x >> 1;                 // 0..512
    const int half = blockIdx.x & 1;
    const int iyr  = (KGRID - iy) & (KGRID - 1);
    const int colA = half ? iyr : iy;                 // output column
    const int colB = half ? iy  : iyr;                // mirror column

    for (int t = tid; t < 4 * KGRID; t += 256) {
        int ix  = t >> 2;
        int p   = t & 3;
        int ixr = (KGRID - ix) & (KGRID - 1);
        const float4 A = *reinterpret_cast<const float4*>(
            &g_grid[(ix  * KGRID + colA) * BATCH + 2 * p]);
        const float4 B = *reinterpret_cast<const float4*>(
            &g_grid[(ixr * KGRID + colB) * BATCH + 2 * p]);
        float2 c;
        c.x = 0.5f * ((A.x + B.x) - (A.w - B.w));
        c.y = 0.5f * ((A.y - B.y) + (A.z + B.z));
        data[p * PITCH + digit_rev10(ix)] = c;
    }
    __syncthreads();

    fft4x1024(data, tw, tid);

    for (int t = tid; t < 4 * 512; t += 256) {
        int xl = t >> 2;                       // compacted row 0..511
        int p  = t & 3;
        int xg = (xl < 256) ? xl : xl + 512;   // source row in smem
        g_fx[(xl * KGRID + colA) * 4 + p] = data[p * PITCH + xg];
    }
}

// ---------------------------------------------------------------------------
__device__ __forceinline__ float inv_apod(int i)
{
    float xv = ((float)i - 256.0f) * (1.0f / 1024.0f);
    float pj = PI_F * 6.0f * xv;
    float tv = BETA_F * BETA_F - pj * pj;
    float st = sqrtf(fabsf(tv));
    float num = (tv > 0.0f) ? sinhf(st) : sinf(st);
    return fmaxf(st, 1e-6f) / num;
}

// FFT along ky on packed data: 1 x row x 4 packed FFTs; 512 blocks.
// Reads g_fx compacted rows; epilogue batch 2p = Re, 2p+1 = Im.
__global__ __launch_bounds__(256, 5)
void fft_y_kernel(float* __restrict__ out)
{
    extern __shared__ float2 sm[];
    float2* tw   = sm;
    float2* data = sm + TW_TOT;
    const int tid = threadIdx.x;
    init_tw(tw, tid, 256);

    const int x_img = blockIdx.x;
    const int x_src = (x_img + 768) & (KGRID - 1);
    const int xl    = (x_src < 256) ? x_src : x_src - 512;   // compacted row
    const float2* grow = &g_fx[xl * (KGRID * 4)];

    for (int t = tid; t < 4 * KGRID; t += 256) {
        int ky = t >> 2;
        int p  = t & 3;
        data[p * PITCH + digit_rev10(ky)] = grow[t];
    }
    __syncthreads();

    fft4x1024(data, tw, tid);

    const float iax = inv_apod(x_img);
    for (int t = tid; t < 4 * NIMG; t += 256) {
        int p  = t >> 9;                       // 0..3
        int yi = t & 511;
        int ys = (yi + 768) & (KGRID - 1);     // in [0,256) U [768,1024)
        float2 v = data[p * PITCH + ys];
        float scale = iax * inv_apod(yi);
        out[(2 * p)     * (NIMG * NIMG) + x_img * NIMG + yi] = v.x * scale;
        out[(2 * p + 1) * (NIMG * NIMG) + x_img * NIMG + yi] = v.y * scale;
    }
}

// ---------------------------------------------------------------------------
extern "C" void kernel_launch(void* const* d_in, const int* in_sizes, int n_in,
                              void* d_out, int out_size)
{
    const float* yr  = (const float*)d_in[0];
    const float* yi  = (const float*)d_in[1];
    const float* uv  = (const float*)d_in[2];
    const float* wts = (const float*)d_in[3];
    float* out = (float*)d_out;

    const int smem_fft = (TW_TOT + 4 * PITCH) * (int)sizeof(float2); // ~40.1 KB
    cudaFuncSetAttribute(fft_x_kernel,
                         cudaFuncAttributeMaxDynamicSharedMemorySize, smem_fft);
    cudaFuncSetAttribute(fft_y_kernel,
                         cudaFuncAttributeMaxDynamicSharedMemorySize, smem_fft);

    zero_kernel<<<4096, 256>>>();
    scatter_kernel<<<(8 * MPTS + 255) / 256, 256>>>(yr, yi, uv, wts);
    fft_x_kernel<<<2 * (KGRID / 2 + 1), 256, smem_fft>>>();
    fft_y_kernel<<<NIMG, 256, smem_fft>>>(out);
}

// round 14
// speedup vs baseline: 1.2597x; 1.1038x over previous
#include <cuda_runtime.h>
#include <math.h>

// ---------------------------------------------------------------------------
// NUFFT adjoint (Kaiser-Bessel gridding) for GB300 — round 14
// = R13 (race-free split-column fft_x -> g_fx, R9 scatter/zero)
// + FFT stage fusion: stages (0,1) and (2,3) each become a register radix-16
//   (one thread owns 16 elements) -> 3 smem round trips instead of 5.
// + padded smem layout pos17(n) = 17*(n>>4) + (n&15), PITCH=1092:
//   conflict-free banks for all fused-stage, stage-4 and IO accesses.
// ---------------------------------------------------------------------------

#define KGRID   1024
#define NIMG    512
#define MPTS    200000
#define BATCH   8
#define JW      6
#define BETA_F  14.04f
#define PI_F    3.14159265358979f

#define GRID_F2 (KGRID * KGRID * BATCH)   // 64 MB
#define FX_F2   (NIMG * KGRID * 4)        // 16 MB packed fft_x output
#define PITCH   1092                      // 17*64 data + 4 pad (PITCH%16==4)

#define TW_OFF1 0
#define TW_OFF2 12
#define TW_OFF3 60
#define TW_OFF4 252
#define TW_TOT  1020

__device__ float2 g_grid[GRID_F2];
__device__ float2 g_fx[FX_F2];            // [xl][ky][p], xl = compacted row

// padded position of logical element n within a row
__device__ __forceinline__ int pos17(int n) { return 17 * (n >> 4) + (n & 15); }

// ---------------------------------------------------------------------------
__device__ __forceinline__ float bessel_i0(float x)
{
    if (x < 3.75f) {
        float t = x * (1.0f / 3.75f);
        t *= t;
        return 1.0f + t * (3.5156229f + t * (3.0899424f + t * (1.2067492f +
                     t * (0.2659732f + t * (0.0360768f + t * 0.0045813f)))));
    } else {
        float t = 3.75f / x;
        float p = 0.39894228f + t * (0.01328592f + t * (0.00225319f +
                  t * (-0.00157565f + t * (0.00916281f + t * (-0.02057706f +
                  t * (0.02635537f + t * (-0.01647633f + t * 0.00392377f)))))));
        return __expf(x) * rsqrtf(x) * p;
    }
}

// ---------------------------------------------------------------------------
// Zero the grid (64 MB). Also the L2 warm for the scatter's atomics.
// ---------------------------------------------------------------------------
__global__ void zero_kernel()
{
    float4* p = reinterpret_cast<float4*>(g_grid);
    const int n = GRID_F2 / 2;
    for (int i = blockIdx.x * blockDim.x + threadIdx.x; i < n;
         i += gridDim.x * blockDim.x)
        p[i] = make_float4(0.f, 0.f, 0.f, 0.f);
}

// ---------------------------------------------------------------------------
// Gridding scatter (R9): 8 threads per measurement; q = batch pair (lanes
// 0-3 write 4 contiguous 16B quarters of each 64B cell), h = x-tap half.
// ---------------------------------------------------------------------------
__global__ __launch_bounds__(256)
void scatter_kernel(const float* __restrict__ yr, const float* __restrict__ yi,
                    const float* __restrict__ uv, const float* __restrict__ wts)
{
    const int gid = blockIdx.x * blockDim.x + threadIdx.x;
    const int m = gid >> 3;
    const int q = gid & 3;                 // batches 2q, 2q+1
    const int h = (gid >> 2) & 1;          // a in {3h, 3h+1, 3h+2}
    if (m >= MPTS) return;

    const float2 c2 = reinterpret_cast<const float2*>(uv)[m];
    const float wt = wts[m];
    const float inv_i0b = 1.0f / bessel_i0(BETA_F);

    int ixv[3], iyv[JW];
    float wx[3], wy[JW];

    {
        float k  = c2.x / (2.0f * PI_F) * (float)KGRID;
        float km = floorf(k - 3.0f);
        #pragma unroll
        for (int j = 0; j < 3; j++) {
            int jj = 3 * h + j;
            float pt = km + (float)(jj + 1);
            float d  = k - pt;
            float arg = fmaxf(1.0f - d * d * (1.0f / 9.0f), 0.0f);
            wx[j] = bessel_i0(BETA_F * sqrtf(arg)) * inv_i0b;
            ixv[j] = ((int)pt + KGRID) & (KGRID - 1);
        }
    }
    {
        float k  = c2.y / (2.0f * PI_F) * (float)KGRID;
        float km = floorf(k - 3.0f);
        #pragma unroll
        for (int j = 0; j < JW; j++) {
            float pt = km + (float)(j + 1);
            float d  = k - pt;
            float arg = fmaxf(1.0f - d * d * (1.0f / 9.0f), 0.0f);
            wy[j] = bessel_i0(BETA_F * sqrtf(arg)) * inv_i0b;
            iyv[j] = ((int)pt + KGRID) & (KGRID - 1);
        }
    }

    const int b0 = 2 * q;
    const float yr0 = yr[b0 * MPTS + m] * wt;
    const float yi0 = yi[b0 * MPTS + m] * wt;
    const float yr1 = yr[(b0 + 1) * MPTS + m] * wt;
    const float yi1 = yi[(b0 + 1) * MPTS + m] * wt;

    #pragma unroll
    for (int a = 0; a < 3; a++) {
        const int rowbase = ixv[a] * KGRID;
        const float wxa = wx[a];
        #pragma unroll
        for (int c = 0; c < JW; c++) {
            const float w2 = wxa * wy[c];
            float* fp = reinterpret_cast<float*>(&g_grid[(rowbase + iyv[c]) * BATCH])
                        + 4 * q;
            asm volatile(
                "red.global.add.v4.f32 [%0], {%1, %2, %3, %4};"
                :: "l"(fp),
                   "f"(w2 * yr0), "f"(w2 * yi0),
                   "f"(w2 * yr1), "f"(w2 * yi1)
                : "memory");
        }
    }
}

// ---------------------------------------------------------------------------
// Radix-4/16 FFT machinery (inverse, e^{+i})
// ---------------------------------------------------------------------------
__device__ __forceinline__ int digit_rev10(int i)
{
    int r = (int)(__brev((unsigned)i) >> 22);
    return ((r & 0x155) << 1) | ((r & 0x2AA) >> 1);
}

__device__ __forceinline__ float2 cmul(float2 a, float2 b)
{
    return make_float2(a.x * b.x - a.y * b.y, a.x * b.y + a.y * b.x);
}

__device__ __forceinline__ void init_tw(float2* tw, int tid, int nthr)
{
    for (int t = tid; t < 340; t += nthr) {
        int s, j, off;
        if      (t < 4)  { s = 1; j = t;      off = TW_OFF1; }
        else if (t < 20) { s = 2; j = t - 4;  off = TW_OFF2; }
        else if (t < 84) { s = 3; j = t - 20; off = TW_OFF3; }
        else             { s = 4; j = t - 84; off = TW_OFF4; }
        int em = j << (8 - 2 * s);
        float a = (float)em * (2.0f * PI_F / 1024.0f);
        float s1, c1, s2, c2, s3, c3;
        __sincosf(a, &s1, &c1);
        __sincosf(2.0f * a, &s2, &c2);
        __sincosf(3.0f * a, &s3, &c3);
        tw[off + 3 * j + 0] = make_float2(c1, s1);
        tw[off + 3 * j + 1] = make_float2(c2, s2);
        tw[off + 3 * j + 2] = make_float2(c3, s3);
    }
}

__device__ __forceinline__ void rad4ip(float2& b0, float2& b1, float2& b2, float2& b3)
{
    float2 t0 = make_float2(b0.x + b2.x, b0.y + b2.y);
    float2 t1 = make_float2(b0.x - b2.x, b0.y - b2.y);
    float2 t2 = make_float2(b1.x + b3.x, b1.y + b3.y);
    float2 t3 = make_float2(-(b1.y - b3.y), b1.x - b3.x);   // +i*(b1-b3)
    b0 = make_float2(t0.x + t2.x, t0.y + t2.y);
    b1 = make_float2(t1.x + t3.x, t1.y + t3.y);
    b2 = make_float2(t0.x - t2.x, t0.y - t2.y);
    b3 = make_float2(t1.x - t3.x, t1.y - t3.y);
}

// stages 0+1 as a register radix-16 on 16 contiguous elements.
// thread: fft row = tid&3, group g = tid>>2; elements n = 16g..16g+15
// (padded: base 17g, contiguous).
__device__ __forceinline__ void stage16_01(float2* data, const float2* tw, int tid)
{
    float2* row = data + (tid & 3) * PITCH;
    const int base = 17 * (tid >> 2);
    float2 v[16];
    #pragma unroll
    for (int k = 0; k < 16; k++) v[k] = row[base + k];

    #pragma unroll
    for (int t = 0; t < 4; t++)                    // stage 0 (twiddle-free)
        rad4ip(v[4 * t], v[4 * t + 1], v[4 * t + 2], v[4 * t + 3]);

    #pragma unroll
    for (int t = 0; t < 4; t++) {                  // stage 1, j = t
        if (t > 0) {
            v[t + 4]  = cmul(v[t + 4],  tw[TW_OFF1 + 3 * t + 0]);
            v[t + 8]  = cmul(v[t + 8],  tw[TW_OFF1 + 3 * t + 1]);
            v[t + 12] = cmul(v[t + 12], tw[TW_OFF1 + 3 * t + 2]);
        }
        rad4ip(v[t], v[t + 4], v[t + 8], v[t + 12]);
    }
    #pragma unroll
    for (int k = 0; k < 16; k++) row[base + k] = v[k];
}

// stages 2+3 as a register radix-16 on stride-16 elements.
// thread: fft row = tid&3, j0 = (tid>>2)&15, c = tid>>6;
// elements n = 256c + 16k + j0 (padded: 272c + 17k + j0).
__device__ __forceinline__ void stage16_23(float2* data, const float2* tw, int tid)
{
    float2* row = data + (tid & 3) * PITCH;
    const int j0 = (tid >> 2) & 15;
    const int c  = tid >> 6;
    const int base = 272 * c + j0;
    float2 v[16];
    #pragma unroll
    for (int k = 0; k < 16; k++) v[k] = row[base + 17 * k];

    {   // stage 2: twiddle j = j0 (same for all 4 butterflies)
        const float2 w1 = tw[TW_OFF2 + 3 * j0 + 0];
        const float2 w2 = tw[TW_OFF2 + 3 * j0 + 1];
        const float2 w3 = tw[TW_OFF2 + 3 * j0 + 2];
        #pragma unroll
        for (int t = 0; t < 4; t++) {
            v[4 * t + 1] = cmul(v[4 * t + 1], w1);
            v[4 * t + 2] = cmul(v[4 * t + 2], w2);
            v[4 * t + 3] = cmul(v[4 * t + 3], w3);
            rad4ip(v[4 * t], v[4 * t + 1], v[4 * t + 2], v[4 * t + 3]);
        }
    }
    #pragma unroll
    for (int t = 0; t < 4; t++) {                  // stage 3: j = 16t + j0
        const int jj = 16 * t + j0;
        v[t + 4]  = cmul(v[t + 4],  tw[TW_OFF3 + 3 * jj + 0]);
        v[t + 8]  = cmul(v[t + 8],  tw[TW_OFF3 + 3 * jj + 1]);
        v[t + 12] = cmul(v[t + 12], tw[TW_OFF3 + 3 * jj + 2]);
        rad4ip(v[t], v[t + 4], v[t + 8], v[t + 12]);
    }
    #pragma unroll
    for (int k = 0; k < 16; k++) row[base + 17 * k] = v[k];
}

// Final stage (S=4), pruned: only outputs in [0,256) (y0) and [768,1024) (y3)
// survive fftshift+crop. Padded addressing: n = j + 256k -> 17(j>>4)+(j&15)+272k.
__device__ __forceinline__ void stage4_last_pruned(float2* x, const float2* tw,
                                                   int bi0)
{
    #pragma unroll
    for (int u = 0; u < 4; u++) {
        const int j = bi0 + (u << 6);
        const int b = 17 * (j >> 4) + (j & 15);
        float2 b0 = x[b];
        float2 b1 = cmul(x[b + 272], tw[TW_OFF4 + 3 * j + 0]);
        float2 b2 = cmul(x[b + 544], tw[TW_OFF4 + 3 * j + 1]);
        float2 b3 = cmul(x[b + 816], tw[TW_OFF4 + 3 * j + 2]);
        float2 t0 = make_float2(b0.x + b2.x, b0.y + b2.y);
        float2 t1 = make_float2(b0.x - b2.x, b0.y - b2.y);
        float2 t2 = make_float2(b1.x + b3.x, b1.y + b3.y);
        float2 t3 = make_float2(-(b1.y - b3.y), b1.x - b3.x);
        x[b]       = make_float2(t0.x + t2.x, t0.y + t2.y);  // y0 (rows 0-255)
        x[b + 816] = make_float2(t1.x - t3.x, t1.y - t3.y);  // y3 (rows 768+)
    }
}

// 4 independent 1024-pt inverse FFTs; 256 threads; padded rows pitch PITCH.
// Caller synced before entry (after its load loop); synced on exit.
__device__ __forceinline__ void fft4x1024(float2* data, const float2* tw, int tid)
{
    stage16_01(data, tw, tid);
    __syncthreads();
    stage16_23(data, tw, tid);
    __syncthreads();
    stage4_last_pruned(data + (tid >> 6) * PITCH, tw, tid & 63);
    __syncthreads();
}

// ---------------------------------------------------------------------------
// FFT along kx on Hermitian-packed batch pairs. Block b: iy = b>>1,
// half = b&1 -> output column colA; 4 packed FFTs; 1026 blocks.
// Reads g_grid (read-only here); writes packed/compacted rows to g_fx.
// ---------------------------------------------------------------------------
__global__ __launch_bounds__(256)
void fft_x_kernel()
{
    extern __shared__ float2 sm[];
    float2* tw   = sm;
    float2* data = sm + TW_TOT;
    const int tid = threadIdx.x;
    init_tw(tw, tid, 256);

    const int iy   = blockIdx.x >> 1;                 // 0..512
    const int half = blockIdx.x & 1;
    const int iyr  = (KGRID - iy) & (KGRID - 1);
    const int colA = half ? iyr : iy;                 // output column
    const int colB = half ? iy  : iyr;                // mirror column

    for (int t = tid; t < 4 * KGRID; t += 256) {
        int ix  = t >> 2;
        int p   = t & 3;
        int ixr = (KGRID - ix) & (KGRID - 1);
        const float4 A = *reinterpret_cast<const float4*>(
            &g_grid[(ix  * KGRID + colA) * BATCH + 2 * p]);
        const float4 B = *reinterpret_cast<const float4*>(
            &g_grid[(ixr * KGRID + colB) * BATCH + 2 * p]);
        float2 c;
        c.x = 0.5f * ((A.x + B.x) - (A.w - B.w));
        c.y = 0.5f * ((A.y - B.y) + (A.z + B.z));
        data[p * PITCH + pos17(digit_rev10(ix))] = c;
    }
    __syncthreads();

    fft4x1024(data, tw, tid);

    for (int t = tid; t < 4 * 512; t += 256) {
        int xl = t >> 2;                       // compacted row 0..511
        int p  = t & 3;
        int xg = (xl < 256) ? xl : xl + 512;   // source row in smem
        g_fx[(xl * KGRID + colA) * 4 + p] = data[p * PITCH + pos17(xg)];
    }
}

// ---------------------------------------------------------------------------
__device__ __forceinline__ float inv_apod(int i)
{
    float xv = ((float)i - 256.0f) * (1.0f / 1024.0f);
    float pj = PI_F * 6.0f * xv;
    float tv = BETA_F * BETA_F - pj * pj;
    float st = sqrtf(fabsf(tv));
    float num = (tv > 0.0f) ? sinhf(st) : sinf(st);
    return fmaxf(st, 1e-6f) / num;
}

// FFT along ky on packed data: 1 x row x 4 packed FFTs; 512 blocks.
// Reads g_fx compacted rows; epilogue batch 2p = Re, 2p+1 = Im.
__global__ __launch_bounds__(256)
void fft_y_kernel(float* __restrict__ out)
{
    extern __shared__ float2 sm[];
    float2* tw   = sm;
    float2* data = sm + TW_TOT;
    const int tid = threadIdx.x;
    init_tw(tw, tid, 256);

    const int x_img = blockIdx.x;
    const int x_src = (x_img + 768) & (KGRID - 1);
    const int xl    = (x_src < 256) ? x_src : x_src - 512;   // compacted row
    const float2* grow = &g_fx[xl * (KGRID * 4)];

    for (int t = tid; t < 4 * KGRID; t += 256) {
        int ky = t >> 2;
        int p  = t & 3;
        data[p * PITCH + pos17(digit_rev10(ky))] = grow[t];
    }
    __syncthreads();

    fft4x1024(data, tw, tid);

    const float iax = inv_apod(x_img);
    for (int t = tid; t < 4 * NIMG; t += 256) {
        int p  = t >> 9;                       // 0..3
        int yi = t & 511;
        int ys = (yi + 768) & (KGRID - 1);     // in [0,256) U [768,1024)
        float2 v = data[p * PITCH + pos17(ys)];
        float scale = iax * inv_apod(yi);
        out[(2 * p)     * (NIMG * NIMG) + x_img * NIMG + yi] = v.x * scale;
        out[(2 * p + 1) * (NIMG * NIMG) + x_img * NIMG + yi] = v.y * scale;
    }
}

// ---------------------------------------------------------------------------
extern "C" void kernel_launch(void* const* d_in, const int* in_sizes, int n_in,
                              void* d_out, int out_size)
{
    const float* yr  = (const float*)d_in[0];
    const float* yi  = (const float*)d_in[1];
    const float* uv  = (const float*)d_in[2];
    const float* wts = (const float*)d_in[3];
    float* out = (float*)d_out;

    const int smem_fft = (TW_TOT + 4 * PITCH) * (int)sizeof(float2); // ~43.1 KB
    cudaFuncSetAttribute(fft_x_kernel,
                         cudaFuncAttributeMaxDynamicSharedMemorySize, smem_fft);
    cudaFuncSetAttribute(fft_y_kernel,
                         cudaFuncAttributeMaxDynamicSharedMemorySize, smem_fft);

    zero_kernel<<<4096, 256>>>();
    scatter_kernel<<<(8 * MPTS + 255) / 256, 256>>>(yr, yi, uv, wts);
    fft_x_kernel<<<2 * (KGRID / 2 + 1), 256, smem_fft>>>();
    fft_y_kernel<<<NIMG, 256, smem_fft>>>(out);
}